// round 3
// baseline (speedup 1.0000x reference)
#include <cuda_runtime.h>

// ---------------------------------------------------------------------------
// TT linear: out[n, vwxyz] = sum x[n,abcde] G1 G2 G3 G4 G5 + bias
// modes in: a=4 b=4 c=8 d=8 e=4 ; out: v=4 w=4 x=8 y=8 z=4 ; ranks 1,8,8,8,8,1
//
// Split at bond k (rank3):
//   L3[k][abc][vwx] = sum_{i,j} G1[a,i,v] G2[b,i,j,w] G3[c,j,k,x]   (8*128*128)
//   R2[k][de][yz]   = sum_{l}   G4[d,k,l,y] G5[e,l,z]               (8*32*32)
// Fused per 4-token CTA, accumulating over k in SMEM:
//   tk[t][de][vwx]  = sum_abc xs[t][abc*32+de] * L3[k][abc][vwx]
//   out[t][vwx*32+yz] += sum_de tk[t][de][vwx] * R2[k][de][yz]
// ---------------------------------------------------------------------------

typedef unsigned long long ull;

__device__ float g_L3[8 * 128 * 128];  // [k][abc][vwx]
__device__ float g_R2[8 * 32 * 32];    // [k][de][yz]

__device__ __forceinline__ void fma2(ull &d, ull a, ull b) {
    asm("fma.rn.f32x2 %0, %1, %2, %0;" : "+l"(d) : "l"(a), "l"(b));
}
__device__ __forceinline__ ull pk2(float x, float y) {
    ull r; asm("mov.b64 %0, {%1, %2};" : "=l"(r) : "f"(x), "f"(y)); return r;
}
__device__ __forceinline__ float2 upk(ull v) {
    float2 f; asm("mov.b64 {%0, %1}, %2;" : "=f"(f.x), "=f"(f.y) : "l"(v)); return f;
}

// ---------------------------------------------------------------------------
// Merge kernel: build L3 and R2 from the 5 cores. Each block builds m12 in
// SMEM redundantly (16K FMA), then blocks partition L3/R2 outputs.
// core0[a,1,i,v]: a*32+i*4+v      core1[b,i,j,w]: b*256+i*32+j*4+w
// core2[c,j,k,x]: c*512+j*64+k*8+x core3[d,k,l,y]: d*512+k*64+l*8+y
// core4[e,l,1,z]: e*32+l*4+z
// ---------------------------------------------------------------------------
__global__ __launch_bounds__(256)
void tt_merge_kernel(const float* __restrict__ c0, const float* __restrict__ c1,
                     const float* __restrict__ c2, const float* __restrict__ c3,
                     const float* __restrict__ c4)
{
    __shared__ float m12[2048];  // [ab][j][vw] = ab*128 + j*16 + vw
    const int tid = threadIdx.x;

    for (int idx = tid; idx < 2048; idx += blockDim.x) {
        int ab = idx >> 7, j = (idx >> 4) & 7, vw = idx & 15;
        int a = ab >> 2, b = ab & 3, v = vw >> 2, w = vw & 3;
        float s = 0.f;
#pragma unroll
        for (int i = 0; i < 8; ++i)
            s += c0[a * 32 + i * 4 + v] * c1[b * 256 + i * 32 + j * 4 + w];
        m12[idx] = s;
    }
    __syncthreads();

    const int stride = gridDim.x * blockDim.x;
    // L3[k][abc][vwx]
    for (int idx = blockIdx.x * blockDim.x + tid; idx < 8 * 128 * 128; idx += stride) {
        int k = idx >> 14, abc = (idx >> 7) & 127, vwx = idx & 127;
        int ab = abc >> 3, c = abc & 7, vw = vwx >> 3, x = vwx & 7;
        float s = 0.f;
#pragma unroll
        for (int j = 0; j < 8; ++j)
            s += m12[ab * 128 + j * 16 + vw] * c2[c * 512 + j * 64 + k * 8 + x];
        g_L3[idx] = s;
    }
    // R2[k][de][yz]
    for (int idx = blockIdx.x * blockDim.x + tid; idx < 8 * 32 * 32; idx += stride) {
        int k = idx >> 10, de = (idx >> 5) & 31, yz = idx & 31;
        int d = de >> 2, e = de & 3, y = yz >> 2, z = yz & 3;
        float s = 0.f;
#pragma unroll
        for (int l = 0; l < 8; ++l)
            s += c3[d * 512 + k * 64 + l * 8 + y] * c4[e * 32 + l * 4 + z];
        g_R2[idx] = s;
    }
}

// ---------------------------------------------------------------------------
// Fused two-stage kernel. 4 tokens per CTA, 512 threads, 1 CTA/SM.
// SMEM (floats): xs[16384] | tk[16384] | l3k[16384] | r2k[1024]  = 200704 B
// ---------------------------------------------------------------------------
__global__ __launch_bounds__(512, 1)
void tt_fused_kernel(const float* __restrict__ x, const float* __restrict__ bias,
                     float* __restrict__ out, int n_tokens)
{
    extern __shared__ float smem[];
    float* xs  = smem;             // [t][4096]
    float* tk  = smem + 16384;     // [t][de][vwx]
    float* l3k = smem + 32768;     // [abc][vwx]  (slice for current k)
    float* r2k = smem + 49152;     // [de][yz]    (slice for current k)

    const int tid = threadIdx.x;
    const int n0  = blockIdx.x * 4;

    // ---- load 4 token rows (64 KB), zero-fill past n_tokens ----
    {
        const float4* xg  = reinterpret_cast<const float4*>(x) + (size_t)n0 * 1024;
        float4*       xs4 = reinterpret_cast<float4*>(xs);
#pragma unroll
        for (int it = 0; it < 8; ++it) {
            int i = tid + it * 512;                 // 0..4095 float4s
            float4 v = make_float4(0.f, 0.f, 0.f, 0.f);
            if (n0 + (i >> 10) < n_tokens) v = xg[i];
            xs4[i] = v;
        }
    }

    // stage-1 mapping: thread owns (t1, de = db*4+0..3, vwx = vb*8+0..7)
    const int t1 = tid >> 7;
    const int r1 = tid & 127;
    const int db = r1 >> 4;        // 0..7
    const int vb = r1 & 15;        // 0..15
    // stage-2 mapping: thread owns (vwx, yz = yzb*8+0..7, all 4 tokens)
    const int yzb = tid >> 7;      // 0..3
    const int vwx = tid & 127;

    ull oacc[16];                  // [t][yz-pair q]: yz = yzb*8 + 2q,2q+1
#pragma unroll
    for (int q = 0; q < 16; ++q) oacc[q] = 0ULL;

    const float4*      xs4b = reinterpret_cast<const float4*>(xs) + t1 * 1024 + db;
    const ulonglong2*  lp2  = reinterpret_cast<const ulonglong2*>(l3k + vb * 8);
    ulonglong2*        tp2  = reinterpret_cast<ulonglong2*>(tk + t1 * 4096 + vb * 8);
    const float*       tkp  = tk + vwx;
    const ulonglong2*  rp2  = reinterpret_cast<const ulonglong2*>(r2k + yzb * 8);

#pragma unroll 1
    for (int k = 0; k < 8; ++k) {
        __syncthreads();  // prev stage-2 done: tk / l3k / r2k reusable

        // ---- load this k's L3 slice (64 KB) + R2 slice (4 KB) ----
        {
            const float4* gs = reinterpret_cast<const float4*>(g_L3 + k * 16384);
            float4*       ds = reinterpret_cast<float4*>(l3k);
#pragma unroll
            for (int it = 0; it < 8; ++it) ds[tid + it * 512] = gs[tid + it * 512];
            if (tid < 256)
                reinterpret_cast<float4*>(r2k)[tid] =
                    reinterpret_cast<const float4*>(g_R2 + k * 1024)[tid];
        }
        __syncthreads();

        // ---- stage 1: tk[t1][de][vwx] = sum_abc xs * l3k ----
        ull acc[16];
#pragma unroll
        for (int q = 0; q < 16; ++q) acc[q] = 0ULL;
#pragma unroll 2
        for (int abc = 0; abc < 128; ++abc) {
            float4 xq = xs4b[abc * 8];                    // x[t1][abc*32 + db*4 ..+3]
            ulonglong2 la = lp2[abc * 32];                // l3k[abc][vb*8 .. +3]
            ulonglong2 lb = lp2[abc * 32 + 1];            // l3k[abc][vb*8+4 .. +7]
            ull a0 = pk2(xq.x, xq.x), a1 = pk2(xq.y, xq.y);
            ull a2 = pk2(xq.z, xq.z), a3 = pk2(xq.w, xq.w);
            fma2(acc[0],  a0, la.x); fma2(acc[1],  a0, la.y);
            fma2(acc[2],  a0, lb.x); fma2(acc[3],  a0, lb.y);
            fma2(acc[4],  a1, la.x); fma2(acc[5],  a1, la.y);
            fma2(acc[6],  a1, lb.x); fma2(acc[7],  a1, lb.y);
            fma2(acc[8],  a2, la.x); fma2(acc[9],  a2, la.y);
            fma2(acc[10], a2, lb.x); fma2(acc[11], a2, lb.y);
            fma2(acc[12], a3, la.x); fma2(acc[13], a3, la.y);
            fma2(acc[14], a3, lb.x); fma2(acc[15], a3, lb.y);
        }
#pragma unroll
        for (int i = 0; i < 4; ++i) {
            int de = db * 4 + i;
            tp2[de * 32]     = make_ulonglong2(acc[i * 4],     acc[i * 4 + 1]);
            tp2[de * 32 + 1] = make_ulonglong2(acc[i * 4 + 2], acc[i * 4 + 3]);
        }
        __syncthreads();

        // ---- stage 2: oacc[t][yz] += sum_de tk[t][de][vwx] * r2k[de][yz] ----
#pragma unroll 2
        for (int de = 0; de < 32; ++de) {
            ulonglong2 ra = rp2[de * 8];       // r2k[de][yzb*8 .. +3]
            ulonglong2 rb = rp2[de * 8 + 1];   // r2k[de][yzb*8+4 .. +7]
            float v0 = tkp[de * 128];
            float v1 = tkp[de * 128 + 4096];
            float v2 = tkp[de * 128 + 8192];
            float v3 = tkp[de * 128 + 12288];
            ull w0 = pk2(v0, v0), w1 = pk2(v1, v1);
            ull w2 = pk2(v2, v2), w3 = pk2(v3, v3);
            fma2(oacc[0],  w0, ra.x); fma2(oacc[1],  w0, ra.y);
            fma2(oacc[2],  w0, rb.x); fma2(oacc[3],  w0, rb.y);
            fma2(oacc[4],  w1, ra.x); fma2(oacc[5],  w1, ra.y);
            fma2(oacc[6],  w1, rb.x); fma2(oacc[7],  w1, rb.y);
            fma2(oacc[8],  w2, ra.x); fma2(oacc[9],  w2, ra.y);
            fma2(oacc[10], w2, rb.x); fma2(oacc[11], w2, rb.y);
            fma2(oacc[12], w3, ra.x); fma2(oacc[13], w3, ra.y);
            fma2(oacc[14], w3, rb.x); fma2(oacc[15], w3, rb.y);
        }
    }

    // ---- epilogue: bias + store ----
    float bl[8];
    {
        const float* bp = bias + vwx * 32 + yzb * 8;
#pragma unroll
        for (int j = 0; j < 8; ++j) bl[j] = bp[j];
    }
#pragma unroll
    for (int t = 0; t < 4; ++t) {
        int tok = n0 + t;
        if (tok >= n_tokens) break;
        float* op = out + (size_t)tok * 4096 + vwx * 32 + yzb * 8;
        float2 p0 = upk(oacc[t * 4]),     p1 = upk(oacc[t * 4 + 1]);
        float2 p2 = upk(oacc[t * 4 + 2]), p3 = upk(oacc[t * 4 + 3]);
        float4 o0 = make_float4(p0.x + bl[0], p0.y + bl[1], p1.x + bl[2], p1.y + bl[3]);
        float4 o1 = make_float4(p2.x + bl[4], p2.y + bl[5], p3.x + bl[6], p3.y + bl[7]);
        *reinterpret_cast<float4*>(op)     = o0;
        *reinterpret_cast<float4*>(op + 4) = o1;
    }
}

// ---------------------------------------------------------------------------
// Inputs (metadata order): input, core0..core4, biases. Output: fp32 [n,4096].
// ---------------------------------------------------------------------------
extern "C" void kernel_launch(void* const* d_in, const int* in_sizes, int n_in,
                              void* d_out, int out_size)
{
    const float* x    = (const float*)d_in[0];
    const float* c0   = (const float*)d_in[1];
    const float* c1   = (const float*)d_in[2];
    const float* c2   = (const float*)d_in[3];
    const float* c3   = (const float*)d_in[4];
    const float* c4   = (const float*)d_in[5];
    const float* bias = (const float*)d_in[6];
    float* out = (float*)d_out;

    const int n_tokens = in_sizes[0] / 4096;
    const int smem_bytes = 50176 * 4;  // 200704 B

    cudaFuncSetAttribute(tt_fused_kernel,
                         cudaFuncAttributeMaxDynamicSharedMemorySize, smem_bytes);

    tt_merge_kernel<<<32, 256>>>(c0, c1, c2, c3, c4);

    const int grid = (n_tokens + 3) / 4;
    tt_fused_kernel<<<grid, 512, smem_bytes>>>(x, bias, out, n_tokens);
}

// round 6
// speedup vs baseline: 3.8153x; 3.8153x over previous
#include <cuda_runtime.h>
#include <cuda_bf16.h>

typedef unsigned int       u32;
typedef unsigned short     u16;
typedef unsigned long long u64;

// ============================================================================
// TT linear via mma.sync (bf16 hi/lo split, 3-product fp32 emulation).
//   L3[k][abc][vwx] = G1*G2*G3 ;  R2[k][de][yz] = G4*G5
//   stage1 (per k): D1'[vwx][(t,de)] = L3k^T[vwx][abc] . X[(t,de)][abc]
//   stage2 (acc k): D2[vwx][t*? yz]  += D1'[vwx][de]   . R2k^T[yz][de]
// Intermediate D1' stays in registers; A2 fragments built with bf16x2 packs.
// ============================================================================

// Padded global operand images (row strides chosen for conflict-free ldmatrix)
__device__ __align__(16) u16 g_L3pad[8][2][17408]; // [k][hi/lo][vwx*136 + abc], 272B rows
__device__ __align__(16) u16 g_R2pad[8][2][1280];  // [k][hi/lo][yz*40 + de],   80B rows

// ---------------- helpers ----------------
__device__ __forceinline__ u32 smem_u32(const void* p) {
    u32 a; asm("{ .reg .u64 t; cvta.to.shared.u64 t, %1; cvt.u32.u64 %0, t; }" : "=r"(a) : "l"(p));
    return a;
}
// pack: low half <- e (first elem), high half <- o (second elem)
__device__ __forceinline__ u32 pack2bf(float e, float o) {
    u32 r; asm("cvt.rn.bf16x2.f32 %0, %1, %2;" : "=r"(r) : "f"(o), "f"(e)); return r;
}
__device__ __forceinline__ u16 f2bf(float v) {
    u16 u; asm("cvt.rn.bf16.f32 %0, %1;" : "=h"(u) : "f"(v)); return u;
}
__device__ __forceinline__ float bf2f(u16 u) { return __uint_as_float(((u32)u) << 16); }

__device__ __forceinline__ void ldsm4(u32& r0, u32& r1, u32& r2, u32& r3, u32 addr) {
    asm volatile("ldmatrix.sync.aligned.m8n8.x4.shared.b16 {%0,%1,%2,%3}, [%4];"
                 : "=r"(r0), "=r"(r1), "=r"(r2), "=r"(r3) : "r"(addr));
}
__device__ __forceinline__ void mma16816(float (&d)[4], u32 a0, u32 a1, u32 a2, u32 a3,
                                         u32 b0, u32 b1) {
    asm volatile("mma.sync.aligned.m16n8k16.row.col.f32.bf16.bf16.f32 "
                 "{%0,%1,%2,%3}, {%4,%5,%6,%7}, {%8,%9}, {%0,%1,%2,%3};"
                 : "+f"(d[0]), "+f"(d[1]), "+f"(d[2]), "+f"(d[3])
                 : "r"(a0), "r"(a1), "r"(a2), "r"(a3), "r"(b0), "r"(b1));
}
__device__ __forceinline__ void cp16(u32 dst, const void* src) {
    asm volatile("cp.async.cg.shared.global [%0], [%1], 16;" :: "r"(dst), "l"(src) : "memory");
}
#define CP_COMMIT() asm volatile("cp.async.commit_group;" ::: "memory")
#define CP_WAIT0()  asm volatile("cp.async.wait_group 0;" ::: "memory")

// ============================================================================
// Merge kernel: build L3/R2 and write hi/lo bf16 padded operand images.
// core0[a,1,i,v]: a*32+i*4+v      core1[b,i,j,w]: b*256+i*32+j*4+w
// core2[c,j,k,x]: c*512+j*64+k*8+x core3[d,k,l,y]: d*512+k*64+l*8+y
// core4[e,l,1,z]: e*32+l*4+z
// ============================================================================
__global__ __launch_bounds__(256)
void tt_merge_kernel(const float* __restrict__ c0, const float* __restrict__ c1,
                     const float* __restrict__ c2, const float* __restrict__ c3,
                     const float* __restrict__ c4)
{
    __shared__ float m12[2048];  // [ab][j][vw]
    const int tid = threadIdx.x;

    for (int idx = tid; idx < 2048; idx += blockDim.x) {
        int ab = idx >> 7, j = (idx >> 4) & 7, vw = idx & 15;
        int a = ab >> 2, b = ab & 3, v = vw >> 2, w = vw & 3;
        float s = 0.f;
#pragma unroll
        for (int i = 0; i < 8; ++i)
            s += c0[a * 32 + i * 4 + v] * c1[b * 256 + i * 32 + j * 4 + w];
        m12[idx] = s;
    }
    __syncthreads();

    const int stride = gridDim.x * blockDim.x;
    // L3: value (k, abc, vwx) -> image row=vwx, col=abc (272B padded rows)
    for (int idx = blockIdx.x * blockDim.x + tid; idx < 8 * 128 * 128; idx += stride) {
        int k = idx >> 14, abc = (idx >> 7) & 127, vwx = idx & 127;
        int ab = abc >> 3, c = abc & 7, vw = vwx >> 3, x = vwx & 7;
        float s = 0.f;
#pragma unroll
        for (int j = 0; j < 8; ++j)
            s += m12[ab * 128 + j * 16 + vw] * c2[c * 512 + j * 64 + k * 8 + x];
        u16 hi = f2bf(s);
        u16 lo = f2bf(s - bf2f(hi));
        g_L3pad[k][0][vwx * 136 + abc] = hi;
        g_L3pad[k][1][vwx * 136 + abc] = lo;
    }
    // R2: value (k, de, yz) -> image row=yz, col=de (80B padded rows)
    for (int idx = blockIdx.x * blockDim.x + tid; idx < 8 * 32 * 32; idx += stride) {
        int k = idx >> 10, yz = (idx >> 5) & 31, de = idx & 31;
        int d = de >> 2, e = de & 3, y = yz >> 2, z = yz & 3;
        float s = 0.f;
#pragma unroll
        for (int l = 0; l < 8; ++l)
            s += c3[d * 512 + k * 64 + l * 8 + y] * c4[e * 32 + l * 4 + z];
        u16 hi = f2bf(s);
        u16 lo = f2bf(s - bf2f(hi));
        g_R2pad[k][0][yz * 40 + de] = hi;
        g_R2pad[k][1][yz * 40 + de] = lo;
    }
}

// ============================================================================
// Fused mma kernel. 4 tokens per CTA, 256 threads (8 warps), 1 CTA/SM.
// SMEM: X images (hi+lo) 69632 | L3 slice (hi+lo, double-use scratch) 69632 |
//       R2 images (all k) 40960  = 180224 B
// ============================================================================
static constexpr int SM_X  = 0;
static constexpr int SM_L3 = 69632;
static constexpr int SM_R2 = 139264;
static constexpr int SMEM_BYTES = 180224;

__global__ __launch_bounds__(256, 1)
void tt_mma_kernel(const float* __restrict__ x, const float* __restrict__ bias,
                   float* __restrict__ out, int n_tokens)
{
    extern __shared__ __align__(16) char smem[];
    const u32 sb = smem_u32(smem);
    const int tid = threadIdx.x, w = tid >> 5, lane = tid & 31;
    const int n0 = blockIdx.x * 4;

    // ---- 1) bulk-copy X rows into scratch (= L3 buffer area), coalesced ----
    {
        const float4* xg = reinterpret_cast<const float4*>(x) + (size_t)n0 * 1024;
        float4* scr = reinterpret_cast<float4*>(smem + SM_L3);
#pragma unroll
        for (int it = 0; it < 16; ++it) {
            int i = tid + it * 256;
            float4 v = make_float4(0.f, 0.f, 0.f, 0.f);
            if (n0 + (i >> 10) < n_tokens) v = xg[i];
            scr[i] = v;
        }
    }
    __syncthreads();

    // ---- 2) build X bf16 hi/lo images: row = t*32+de, col = abc, 272B rows ----
    {
        const int t = w >> 1, ab0 = (w & 1) * 64;
        const float* s = reinterpret_cast<const float*>(smem + SM_L3) + t * 4096 + lane;
        const int row = t * 32 + lane;
        char* xh = smem + SM_X + row * 272;
        char* xl = xh + 34816;
#pragma unroll 8
        for (int a2i = 0; a2i < 32; ++a2i) {
            int cc = ab0 + 2 * a2i;
            float f0 = s[cc * 32];        // X[row][cc]   = x[n0+t][cc*32+de]
            float f1 = s[cc * 32 + 32];   // X[row][cc+1]
            u32 hw = pack2bf(f0, f1);
            float h0 = __uint_as_float(hw << 16);
            float h1 = __uint_as_float(hw & 0xFFFF0000u);
            u32 lw = pack2bf(f0 - h0, f1 - h1);
            *reinterpret_cast<u32*>(xh + cc * 2) = hw;
            *reinterpret_cast<u32*>(xl + cc * 2) = lw;
        }
    }
    __syncthreads();   // scratch consumed; safe to overwrite with L3 k=0

    // ---- 3) async load: all R2 images + L3 slice k=0 ----
    {
        const char* gr = reinterpret_cast<const char*>(&g_R2pad[0][0][0]);
#pragma unroll
        for (int it = 0; it < 10; ++it) { int i = tid + it * 256; cp16(sb + SM_R2 + i * 16, gr + i * 16); }
        const char* gl = reinterpret_cast<const char*>(&g_L3pad[0][0][0]);
#pragma unroll
        for (int it = 0; it < 17; ++it) { int i = tid + it * 256; cp16(sb + SM_L3 + i * 16, gl + i * 16); }
        CP_COMMIT();
    }

    // ---- per-lane ldmatrix address offsets ----
    const u32 a_lane = (u32)((((lane & 7) | (lane & 8)) * 272) + ((lane & 16) ? 16 : 0));
    const u32 b_lane = (u32)((((lane & 7) + ((lane & 16) ? 8 : 0)) * 272) + ((lane & 8) ? 16 : 0));
    const u32 r_lane = (u32)((((lane & 7) + ((lane & 16) ? 8 : 0)) * 80)  + ((lane & 8) ? 16 : 0));
    const u32 aw    = sb + SM_L3 + (u32)(w * 16 * 272) + a_lane;
    const u32 bbase = sb + SM_X + b_lane;
    const u32 rbase = sb + SM_R2 + r_lane;

    float d2[4][4][4];   // [token][yz n-tile][c-frag]
#pragma unroll
    for (int t = 0; t < 4; ++t)
#pragma unroll
        for (int jn = 0; jn < 4; ++jn)
#pragma unroll
            for (int q = 0; q < 4; ++q) d2[t][jn][q] = 0.f;

#pragma unroll 1
    for (int k = 0; k < 8; ++k) {
        CP_WAIT0();
        __syncthreads();   // L3 slice k resident

        // ---- stage 1: D1'[vwx 16-row strip][tde 128] = sum_abc L3^T . X ----
        float acc[16][4];
#pragma unroll
        for (int n = 0; n < 16; ++n)
#pragma unroll
            for (int q = 0; q < 4; ++q) acc[n][q] = 0.f;

#pragma unroll 1
        for (int p = 0; p < 3; ++p) {   // (Ah,Bh), (Ah,Bl), (Al,Bh)
            const u32 ab = aw    + ((p == 2) ? 34816u : 0u);
            const u32 bb = bbase + ((p == 1) ? 34816u : 0u);
#pragma unroll 1
            for (int kk = 0; kk < 8; ++kk) {
                u32 a0, a1, a2r, a3;
                ldsm4(a0, a1, a2r, a3, ab + kk * 32);
#pragma unroll
                for (int j = 0; j < 8; ++j) {
                    u32 r0, r1, r2, r3;
                    ldsm4(r0, r1, r2, r3, bb + j * 4352 + kk * 32);
                    mma16816(acc[2 * j],     a0, a1, a2r, a3, r0, r1);
                    mma16816(acc[2 * j + 1], a0, a1, a2r, a3, r2, r3);
                }
            }
        }
        __syncthreads();   // all warps done reading L3 slice k

        // ---- prefetch L3 slice k+1 (overlaps with stage 2) ----
        if (k < 7) {
            const char* gl = reinterpret_cast<const char*>(&g_L3pad[k + 1][0][0]);
#pragma unroll
            for (int it = 0; it < 17; ++it) { int i = tid + it * 256; cp16(sb + SM_L3 + i * 16, gl + i * 16); }
            CP_COMMIT();
        }

        // ---- stage 2: D2[vwx][yz] += D1'[vwx][de] . R2k^T, per token ----
        const u32 rk = rbase + (u32)(k * 5120);
#pragma unroll
        for (int p = 0; p < 3; ++p) {
            const u32 rb = rk + ((p == 1) ? 2560u : 0u);   // B img: lo only for p1
            u32 b2[4][2][2];
#pragma unroll
            for (int i = 0; i < 2; ++i)
#pragma unroll
                for (int kk = 0; kk < 2; ++kk) {
                    u32 r0, r1, r2, r3;
                    ldsm4(r0, r1, r2, r3, rb + i * 1280 + kk * 32);
                    b2[2 * i][kk][0] = r0; b2[2 * i][kk][1] = r1;
                    b2[2 * i + 1][kk][0] = r2; b2[2 * i + 1][kk][1] = r3;
                }
#pragma unroll
            for (int t = 0; t < 4; ++t) {
                // build A2 frags (hi for p0/p1, lo for p2) from stage-1 accumulators
                u32 a2[2][4];
#pragma unroll
                for (int kk = 0; kk < 2; ++kk) {
                    const float* cA = acc[4 * t + 2 * kk];
                    const float* cB = acc[4 * t + 2 * kk + 1];
                    u32 h0 = pack2bf(cA[0], cA[1]);
                    u32 h1 = pack2bf(cA[2], cA[3]);
                    u32 h2 = pack2bf(cB[0], cB[1]);
                    u32 h3 = pack2bf(cB[2], cB[3]);
                    if (p < 2) {
                        a2[kk][0] = h0; a2[kk][1] = h1; a2[kk][2] = h2; a2[kk][3] = h3;
                    } else {
                        a2[kk][0] = pack2bf(cA[0] - __uint_as_float(h0 << 16),
                                            cA[1] - __uint_as_float(h0 & 0xFFFF0000u));
                        a2[kk][1] = pack2bf(cA[2] - __uint_as_float(h1 << 16),
                                            cA[3] - __uint_as_float(h1 & 0xFFFF0000u));
                        a2[kk][2] = pack2bf(cB[0] - __uint_as_float(h2 << 16),
                                            cB[1] - __uint_as_float(h2 & 0xFFFF0000u));
                        a2[kk][3] = pack2bf(cB[2] - __uint_as_float(h3 << 16),
                                            cB[3] - __uint_as_float(h3 & 0xFFFF0000u));
                    }
                }
#pragma unroll
                for (int kk = 0; kk < 2; ++kk)
#pragma unroll
                    for (int jn = 0; jn < 4; ++jn)
                        mma16816(d2[t][jn], a2[kk][0], a2[kk][1], a2[kk][2], a2[kk][3],
                                 b2[jn][kk][0], b2[jn][kk][1]);
            }
        }
    }

    // ---- epilogue: bias + store. c-frag: rows vwx0, vwx0+8; cols 8*jn+2*tg ----
    const int g = lane >> 2, tg = lane & 3;
    const int vwx0 = 16 * w + g;
    float2 bv0[4], bv1[4];
#pragma unroll
    for (int jn = 0; jn < 4; ++jn) {
        bv0[jn] = *reinterpret_cast<const float2*>(bias + vwx0 * 32 + 8 * jn + 2 * tg);
        bv1[jn] = *reinterpret_cast<const float2*>(bias + (vwx0 + 8) * 32 + 8 * jn + 2 * tg);
    }
#pragma unroll
    for (int t = 0; t < 4; ++t) {
        if (n0 + t < n_tokens) {
            float* o = out + (size_t)(n0 + t) * 4096;
#pragma unroll
            for (int jn = 0; jn < 4; ++jn) {
                float2 v0 = make_float2(d2[t][jn][0] + bv0[jn].x, d2[t][jn][1] + bv0[jn].y);
                float2 v1 = make_float2(d2[t][jn][2] + bv1[jn].x, d2[t][jn][3] + bv1[jn].y);
                *reinterpret_cast<float2*>(o + vwx0 * 32 + 8 * jn + 2 * tg) = v0;
                *reinterpret_cast<float2*>(o + (vwx0 + 8) * 32 + 8 * jn + 2 * tg) = v1;
            }
        }
    }
}

// ============================================================================
// Launch. Inputs: input, core0..core4, biases. Output fp32 [n, 4096].
// ============================================================================
extern "C" void kernel_launch(void* const* d_in, const int* in_sizes, int n_in,
                              void* d_out, int out_size)
{
    const float* x    = (const float*)d_in[0];
    const float* c0   = (const float*)d_in[1];
    const float* c1   = (const float*)d_in[2];
    const float* c2   = (const float*)d_in[3];
    const float* c3   = (const float*)d_in[4];
    const float* c4   = (const float*)d_in[5];
    const float* bias = (const float*)d_in[6];
    float* out = (float*)d_out;

    const int n_tokens = in_sizes[0] / 4096;

    cudaFuncSetAttribute(tt_mma_kernel,
                         cudaFuncAttributeMaxDynamicSharedMemorySize, SMEM_BYTES);

    tt_merge_kernel<<<32, 256>>>(c0, c1, c2, c3, c4);

    const int grid = (n_tokens + 3) / 4;
    tt_mma_kernel<<<grid, 256, SMEM_BYTES>>>(x, bias, out, n_tokens);
}

// round 7
// speedup vs baseline: 3.8171x; 1.0005x over previous
#include <cuda_runtime.h>
#include <cuda_bf16.h>

typedef unsigned int       u32;
typedef unsigned short     u16;
typedef unsigned long long u64;

// ============================================================================
// TT linear via mma.sync (bf16 hi/lo split, 3-product fp32 emulation).
//   L3[k][abc][vwx] = G1*G2*G3 ;  R2[k][de][yz] = G4*G5
//   stage1 (per k): D1'[vwx][(t,de)] = L3k^T[vwx][abc] . X[(t,de)][abc]
//   stage2 (acc k): D2[vwx][t*? yz]  += D1'[vwx][de]   . R2k^T[yz][de]
// Intermediate D1' stays in registers; A2 fragments built with bf16x2 packs.
// ============================================================================

// Padded global operand images (row strides chosen for conflict-free ldmatrix)
__device__ __align__(16) u16 g_L3pad[8][2][17408]; // [k][hi/lo][vwx*136 + abc], 272B rows
__device__ __align__(16) u16 g_R2pad[8][2][1280];  // [k][hi/lo][yz*40 + de],   80B rows

// ---------------- helpers ----------------
__device__ __forceinline__ u32 smem_u32(const void* p) {
    u32 a; asm("{ .reg .u64 t; cvta.to.shared.u64 t, %1; cvt.u32.u64 %0, t; }" : "=r"(a) : "l"(p));
    return a;
}
// pack: low half <- e (first elem), high half <- o (second elem)
__device__ __forceinline__ u32 pack2bf(float e, float o) {
    u32 r; asm("cvt.rn.bf16x2.f32 %0, %1, %2;" : "=r"(r) : "f"(o), "f"(e)); return r;
}
__device__ __forceinline__ u16 f2bf(float v) {
    u16 u; asm("cvt.rn.bf16.f32 %0, %1;" : "=h"(u) : "f"(v)); return u;
}
__device__ __forceinline__ float bf2f(u16 u) { return __uint_as_float(((u32)u) << 16); }

__device__ __forceinline__ void ldsm4(u32& r0, u32& r1, u32& r2, u32& r3, u32 addr) {
    asm volatile("ldmatrix.sync.aligned.m8n8.x4.shared.b16 {%0,%1,%2,%3}, [%4];"
                 : "=r"(r0), "=r"(r1), "=r"(r2), "=r"(r3) : "r"(addr));
}
__device__ __forceinline__ void mma16816(float (&d)[4], u32 a0, u32 a1, u32 a2, u32 a3,
                                         u32 b0, u32 b1) {
    asm volatile("mma.sync.aligned.m16n8k16.row.col.f32.bf16.bf16.f32 "
                 "{%0,%1,%2,%3}, {%4,%5,%6,%7}, {%8,%9}, {%0,%1,%2,%3};"
                 : "+f"(d[0]), "+f"(d[1]), "+f"(d[2]), "+f"(d[3])
                 : "r"(a0), "r"(a1), "r"(a2), "r"(a3), "r"(b0), "r"(b1));
}
__device__ __forceinline__ void cp16(u32 dst, const void* src) {
    asm volatile("cp.async.cg.shared.global [%0], [%1], 16;" :: "r"(dst), "l"(src) : "memory");
}
#define CP_COMMIT() asm volatile("cp.async.commit_group;" ::: "memory")
#define CP_WAIT0()  asm volatile("cp.async.wait_group 0;" ::: "memory")

// ============================================================================
// Merge kernel: build L3/R2 and write hi/lo bf16 padded operand images.
// core0[a,1,i,v]: a*32+i*4+v      core1[b,i,j,w]: b*256+i*32+j*4+w
// core2[c,j,k,x]: c*512+j*64+k*8+x core3[d,k,l,y]: d*512+k*64+l*8+y
// core4[e,l,1,z]: e*32+l*4+z
// ============================================================================
__global__ __launch_bounds__(256)
void tt_merge_kernel(const float* __restrict__ c0, const float* __restrict__ c1,
                     const float* __restrict__ c2, const float* __restrict__ c3,
                     const float* __restrict__ c4)
{
    __shared__ float m12[2048];  // [ab][j][vw]
    const int tid = threadIdx.x;

    for (int idx = tid; idx < 2048; idx += blockDim.x) {
        int ab = idx >> 7, j = (idx >> 4) & 7, vw = idx & 15;
        int a = ab >> 2, b = ab & 3, v = vw >> 2, w = vw & 3;
        float s = 0.f;
#pragma unroll
        for (int i = 0; i < 8; ++i)
            s += c0[a * 32 + i * 4 + v] * c1[b * 256 + i * 32 + j * 4 + w];
        m12[idx] = s;
    }
    __syncthreads();

    const int stride = gridDim.x * blockDim.x;
    // L3: value (k, abc, vwx) -> image row=vwx, col=abc (272B padded rows)
    for (int idx = blockIdx.x * blockDim.x + tid; idx < 8 * 128 * 128; idx += stride) {
        int k = idx >> 14, abc = (idx >> 7) & 127, vwx = idx & 127;
        int ab = abc >> 3, c = abc & 7, vw = vwx >> 3, x = vwx & 7;
        float s = 0.f;
#pragma unroll
        for (int j = 0; j < 8; ++j)
            s += m12[ab * 128 + j * 16 + vw] * c2[c * 512 + j * 64 + k * 8 + x];
        u16 hi = f2bf(s);
        u16 lo = f2bf(s - bf2f(hi));
        g_L3pad[k][0][vwx * 136 + abc] = hi;
        g_L3pad[k][1][vwx * 136 + abc] = lo;
    }
    // R2: value (k, de, yz) -> image row=yz, col=de (80B padded rows)
    for (int idx = blockIdx.x * blockDim.x + tid; idx < 8 * 32 * 32; idx += stride) {
        int k = idx >> 10, yz = (idx >> 5) & 31, de = idx & 31;
        int d = de >> 2, e = de & 3, y = yz >> 2, z = yz & 3;
        float s = 0.f;
#pragma unroll
        for (int l = 0; l < 8; ++l)
            s += c3[d * 512 + k * 64 + l * 8 + y] * c4[e * 32 + l * 4 + z];
        u16 hi = f2bf(s);
        u16 lo = f2bf(s - bf2f(hi));
        g_R2pad[k][0][yz * 40 + de] = hi;
        g_R2pad[k][1][yz * 40 + de] = lo;
    }
}

// ============================================================================
// Fused mma kernel. 4 tokens per CTA, 256 threads (8 warps), 1 CTA/SM.
// SMEM: X images (hi+lo) 69632 | L3 slice (hi+lo, double-use scratch) 69632 |
//       R2 images (all k) 40960  = 180224 B
// ============================================================================
static constexpr int SM_X  = 0;
static constexpr int SM_L3 = 69632;
static constexpr int SM_R2 = 139264;
static constexpr int SMEM_BYTES = 180224;

__global__ __launch_bounds__(256, 1)
void tt_mma_kernel(const float* __restrict__ x, const float* __restrict__ bias,
                   float* __restrict__ out, int n_tokens)
{
    extern __shared__ __align__(16) char smem[];
    const u32 sb = smem_u32(smem);
    const int tid = threadIdx.x, w = tid >> 5, lane = tid & 31;
    const int n0 = blockIdx.x * 4;

    // ---- 1) bulk-copy X rows into scratch (= L3 buffer area), coalesced ----
    {
        const float4* xg = reinterpret_cast<const float4*>(x) + (size_t)n0 * 1024;
        float4* scr = reinterpret_cast<float4*>(smem + SM_L3);
#pragma unroll
        for (int it = 0; it < 16; ++it) {
            int i = tid + it * 256;
            float4 v = make_float4(0.f, 0.f, 0.f, 0.f);
            if (n0 + (i >> 10) < n_tokens) v = xg[i];
            scr[i] = v;
        }
    }
    __syncthreads();

    // ---- 2) build X bf16 hi/lo images: row = t*32+de, col = abc, 272B rows ----
    {
        const int t = w >> 1, ab0 = (w & 1) * 64;
        const float* s = reinterpret_cast<const float*>(smem + SM_L3) + t * 4096 + lane;
        const int row = t * 32 + lane;
        char* xh = smem + SM_X + row * 272;
        char* xl = xh + 34816;
#pragma unroll 8
        for (int a2i = 0; a2i < 32; ++a2i) {
            int cc = ab0 + 2 * a2i;
            float f0 = s[cc * 32];        // X[row][cc]   = x[n0+t][cc*32+de]
            float f1 = s[cc * 32 + 32];   // X[row][cc+1]
            u32 hw = pack2bf(f0, f1);
            float h0 = __uint_as_float(hw << 16);
            float h1 = __uint_as_float(hw & 0xFFFF0000u);
            u32 lw = pack2bf(f0 - h0, f1 - h1);
            *reinterpret_cast<u32*>(xh + cc * 2) = hw;
            *reinterpret_cast<u32*>(xl + cc * 2) = lw;
        }
    }
    __syncthreads();   // scratch consumed; safe to overwrite with L3 k=0

    // ---- 3) async load: all R2 images + L3 slice k=0 ----
    {
        const char* gr = reinterpret_cast<const char*>(&g_R2pad[0][0][0]);
#pragma unroll
        for (int it = 0; it < 10; ++it) { int i = tid + it * 256; cp16(sb + SM_R2 + i * 16, gr + i * 16); }
        const char* gl = reinterpret_cast<const char*>(&g_L3pad[0][0][0]);
#pragma unroll
        for (int it = 0; it < 17; ++it) { int i = tid + it * 256; cp16(sb + SM_L3 + i * 16, gl + i * 16); }
        CP_COMMIT();
    }

    // ---- per-lane ldmatrix address offsets ----
    const u32 a_lane = (u32)((((lane & 7) | (lane & 8)) * 272) + ((lane & 16) ? 16 : 0));
    const u32 b_lane = (u32)((((lane & 7) + ((lane & 16) ? 8 : 0)) * 272) + ((lane & 8) ? 16 : 0));
    const u32 r_lane = (u32)((((lane & 7) + ((lane & 16) ? 8 : 0)) * 80)  + ((lane & 8) ? 16 : 0));
    const u32 aw    = sb + SM_L3 + (u32)(w * 16 * 272) + a_lane;
    const u32 bbase = sb + SM_X + b_lane;
    const u32 rbase = sb + SM_R2 + r_lane;

    float d2[4][4][4];   // [token][yz n-tile][c-frag]
#pragma unroll
    for (int t = 0; t < 4; ++t)
#pragma unroll
        for (int jn = 0; jn < 4; ++jn)
#pragma unroll
            for (int q = 0; q < 4; ++q) d2[t][jn][q] = 0.f;

#pragma unroll 1
    for (int k = 0; k < 8; ++k) {
        CP_WAIT0();
        __syncthreads();   // L3 slice k resident

        // ---- stage 1: D1'[vwx 16-row strip][tde 128] = sum_abc L3^T . X ----
        float acc[16][4];
#pragma unroll
        for (int n = 0; n < 16; ++n)
#pragma unroll
            for (int q = 0; q < 4; ++q) acc[n][q] = 0.f;

#pragma unroll 1
        for (int p = 0; p < 3; ++p) {   // (Ah,Bh), (Ah,Bl), (Al,Bh)
            const u32 ab = aw    + ((p == 2) ? 34816u : 0u);
            const u32 bb = bbase + ((p == 1) ? 34816u : 0u);
#pragma unroll 1
            for (int kk = 0; kk < 8; ++kk) {
                u32 a0, a1, a2r, a3;
                ldsm4(a0, a1, a2r, a3, ab + kk * 32);
#pragma unroll
                for (int j = 0; j < 8; ++j) {
                    u32 r0, r1, r2, r3;
                    ldsm4(r0, r1, r2, r3, bb + j * 4352 + kk * 32);
                    mma16816(acc[2 * j],     a0, a1, a2r, a3, r0, r1);
                    mma16816(acc[2 * j + 1], a0, a1, a2r, a3, r2, r3);
                }
            }
        }
        __syncthreads();   // all warps done reading L3 slice k

        // ---- prefetch L3 slice k+1 (overlaps with stage 2) ----
        if (k < 7) {
            const char* gl = reinterpret_cast<const char*>(&g_L3pad[k + 1][0][0]);
#pragma unroll
            for (int it = 0; it < 17; ++it) { int i = tid + it * 256; cp16(sb + SM_L3 + i * 16, gl + i * 16); }
            CP_COMMIT();
        }

        // ---- stage 2: D2[vwx][yz] += D1'[vwx][de] . R2k^T, per token ----
        const u32 rk = rbase + (u32)(k * 5120);
#pragma unroll
        for (int p = 0; p < 3; ++p) {
            const u32 rb = rk + ((p == 1) ? 2560u : 0u);   // B img: lo only for p1
            u32 b2[4][2][2];
#pragma unroll
            for (int i = 0; i < 2; ++i)
#pragma unroll
                for (int kk = 0; kk < 2; ++kk) {
                    u32 r0, r1, r2, r3;
                    ldsm4(r0, r1, r2, r3, rb + i * 1280 + kk * 32);
                    b2[2 * i][kk][0] = r0; b2[2 * i][kk][1] = r1;
                    b2[2 * i + 1][kk][0] = r2; b2[2 * i + 1][kk][1] = r3;
                }
#pragma unroll
            for (int t = 0; t < 4; ++t) {
                // build A2 frags (hi for p0/p1, lo for p2) from stage-1 accumulators
                u32 a2[2][4];
#pragma unroll
                for (int kk = 0; kk < 2; ++kk) {
                    const float* cA = acc[4 * t + 2 * kk];
                    const float* cB = acc[4 * t + 2 * kk + 1];
                    u32 h0 = pack2bf(cA[0], cA[1]);
                    u32 h1 = pack2bf(cA[2], cA[3]);
                    u32 h2 = pack2bf(cB[0], cB[1]);
                    u32 h3 = pack2bf(cB[2], cB[3]);
                    if (p < 2) {
                        a2[kk][0] = h0; a2[kk][1] = h1; a2[kk][2] = h2; a2[kk][3] = h3;
                    } else {
                        a2[kk][0] = pack2bf(cA[0] - __uint_as_float(h0 << 16),
                                            cA[1] - __uint_as_float(h0 & 0xFFFF0000u));
                        a2[kk][1] = pack2bf(cA[2] - __uint_as_float(h1 << 16),
                                            cA[3] - __uint_as_float(h1 & 0xFFFF0000u));
                        a2[kk][2] = pack2bf(cB[0] - __uint_as_float(h2 << 16),
                                            cB[1] - __uint_as_float(h2 & 0xFFFF0000u));
                        a2[kk][3] = pack2bf(cB[2] - __uint_as_float(h3 << 16),
                                            cB[3] - __uint_as_float(h3 & 0xFFFF0000u));
                    }
                }
#pragma unroll
                for (int kk = 0; kk < 2; ++kk)
#pragma unroll
                    for (int jn = 0; jn < 4; ++jn)
                        mma16816(d2[t][jn], a2[kk][0], a2[kk][1], a2[kk][2], a2[kk][3],
                                 b2[jn][kk][0], b2[jn][kk][1]);
            }
        }
    }

    // ---- epilogue: bias + store. c-frag: rows vwx0, vwx0+8; cols 8*jn+2*tg ----
    const int g = lane >> 2, tg = lane & 3;
    const int vwx0 = 16 * w + g;
    float2 bv0[4], bv1[4];
#pragma unroll
    for (int jn = 0; jn < 4; ++jn) {
        bv0[jn] = *reinterpret_cast<const float2*>(bias + vwx0 * 32 + 8 * jn + 2 * tg);
        bv1[jn] = *reinterpret_cast<const float2*>(bias + (vwx0 + 8) * 32 + 8 * jn + 2 * tg);
    }
#pragma unroll
    for (int t = 0; t < 4; ++t) {
        if (n0 + t < n_tokens) {
            float* o = out + (size_t)(n0 + t) * 4096;
#pragma unroll
            for (int jn = 0; jn < 4; ++jn) {
                float2 v0 = make_float2(d2[t][jn][0] + bv0[jn].x, d2[t][jn][1] + bv0[jn].y);
                float2 v1 = make_float2(d2[t][jn][2] + bv1[jn].x, d2[t][jn][3] + bv1[jn].y);
                *reinterpret_cast<float2*>(o + vwx0 * 32 + 8 * jn + 2 * tg) = v0;
                *reinterpret_cast<float2*>(o + (vwx0 + 8) * 32 + 8 * jn + 2 * tg) = v1;
            }
        }
    }
}

// ============================================================================
// Launch. Inputs: input, core0..core4, biases. Output fp32 [n, 4096].
// ============================================================================
extern "C" void kernel_launch(void* const* d_in, const int* in_sizes, int n_in,
                              void* d_out, int out_size)
{
    const float* x    = (const float*)d_in[0];
    const float* c0   = (const float*)d_in[1];
    const float* c1   = (const float*)d_in[2];
    const float* c2   = (const float*)d_in[3];
    const float* c3   = (const float*)d_in[4];
    const float* c4   = (const float*)d_in[5];
    const float* bias = (const float*)d_in[6];
    float* out = (float*)d_out;

    const int n_tokens = in_sizes[0] / 4096;

    cudaFuncSetAttribute(tt_mma_kernel,
                         cudaFuncAttributeMaxDynamicSharedMemorySize, SMEM_BYTES);

    tt_merge_kernel<<<32, 256>>>(c0, c1, c2, c3, c4);

    const int grid = (n_tokens + 3) / 4;
    tt_mma_kernel<<<grid, 256, SMEM_BYTES>>>(x, bias, out, n_tokens);
}